// round 2
// baseline (speedup 1.0000x reference)
#include <cuda_runtime.h>
#include <math.h>

#define CIN      16
#define COUT     32
#define TAPS     64
#define KDIM     (TAPS * CIN)     // 1024
#define VPB      16               // voxels per block
#define THREADS  256
#define A_STRIDE 1028             // 1024 + 4 pad (bank-shift rows by 4 banks)

// dynamic smem layout:
//  W_s   : KDIM*COUT floats (131072 B), layout [k][cout], k = tap*16+cin
//  A_s   : VPB * A_STRIDE floats (65792 B), acc[v][tap*16+cin]
//  den_s : VPB floats
#define SMEM_FLOATS (KDIM * COUT + VPB * A_STRIDE + VPB)

extern __shared__ float smem[];

__global__ void __launch_bounds__(THREADS, 1)
cconv_kernel(const float* __restrict__ feats,
             const float* __restrict__ inp_points,
             const float* __restrict__ out_points,
             const float* __restrict__ out_extents,
             const float* __restrict__ scale_compat,
             const float* __restrict__ nbr_dist,
             const int*   __restrict__ nbr_idx,
             const int*   __restrict__ row_splits,
             const float* __restrict__ Wg,
             const float* __restrict__ bias,
             float*       __restrict__ out,
             int n_out)
{
    float* W_s   = smem;
    float* A_s   = smem + KDIM * COUT;
    float* den_s = A_s + VPB * A_STRIDE;

    const int tid  = threadIdx.x;
    const int warp = tid >> 5;
    const int lane = tid & 31;

    // ---- load W into shared (coalesced float4 copy; L2-resident after wave 1) ----
    {
        const float4* Wg4 = reinterpret_cast<const float4*>(Wg);
        float4*       Ws4 = reinterpret_cast<float4*>(W_s);
        #pragma unroll
        for (int i = 0; i < (KDIM * COUT / 4) / THREADS; ++i)
            Ws4[tid + i * THREADS] = Wg4[tid + i * THREADS];
    }

    // ---- phase 1: per-warp voxel scatter into shared acc (no atomics) ----
    const int ch    = lane & 15;   // channel 0..15
    const int chalf = lane >> 4;   // corner-half 0/1

    for (int vi = 0; vi < 2; ++vi) {
        const int vloc = warp * 2 + vi;
        const int v    = blockIdx.x * VPB + vloc;
        float* acc = A_s + vloc * A_STRIDE;

        // zero acc row (1024 floats, float4, 32 lanes -> 8 iters)
        float4* acc4 = reinterpret_cast<float4*>(acc);
        #pragma unroll
        for (int i = 0; i < (KDIM / 4) / 32; ++i)
            acc4[lane + i * 32] = make_float4(0.f, 0.f, 0.f, 0.f);

        float den = 0.f;
        if (v < n_out) {
            const int e0 = row_splits[v];
            const int e1 = row_splits[v + 1];
            const float ox = out_points[v * 3 + 0];
            const float oy = out_points[v * 3 + 1];
            const float oz = out_points[v * 3 + 2];
            const float inv_r = 2.0f / out_extents[v];  // 1/(0.5*extent)

            for (int e = e0; e < e1; ++e) {
                // scalar per-edge geometry, computed redundantly in all lanes
                const float sc = scale_compat[e];
                const float d  = nbr_dist[e];
                float omr = 1.0f - d;
                float w6  = omr * omr * omr;
                w6 = fminf(fmaxf(w6, 0.0f), 1.0f);
                const float imp = sc * w6;
                den += imp;

                const int nb = nbr_idx[e];
                const float rx = (inp_points[nb * 3 + 0] - ox) * inv_r;
                const float ry = (inp_points[nb * 3 + 1] - oy) * inv_r;
                const float rz = (inp_points[nb * 3 + 2] - oz) * inv_r;

                const float l2   = sqrtf(rx * rx + ry * ry + rz * rz);
                const float linf = fmaxf(fabsf(rx), fmaxf(fabsf(ry), fabsf(rz)));
                const float s    = (linf > 0.0f) ? (l2 / fmaxf(linf, 1e-12f)) : 0.0f;

                const float q0 = fminf(fmaxf(rx * s, -1.0f), 1.0f);
                const float q1 = fminf(fmaxf(ry * s, -1.0f), 1.0f);
                const float q2 = fminf(fmaxf(rz * s, -1.0f), 1.0f);

                const float t0 = (q0 + 1.0f) * 1.5f;
                const float t1 = (q1 + 1.0f) * 1.5f;
                const float t2 = (q2 + 1.0f) * 1.5f;

                float fl0 = fminf(fmaxf(floorf(t0), 0.0f), 2.0f);
                float fl1 = fminf(fmaxf(floorf(t1), 0.0f), 2.0f);
                float fl2 = fminf(fmaxf(floorf(t2), 0.0f), 2.0f);
                const int i0x = (int)fl0;
                const int i0y = (int)fl1;
                const int i0z = (int)fl2;
                const float f0 = t0 - fl0;
                const float f1 = t1 - fl1;
                const float f2 = t2 - fl2;

                // per-channel weighted feature
                const float psi = imp * feats[nb * CIN + ch];

                // 8 corners: half-warps take corners {chalf, 2+chalf, 4+chalf, 6+chalf}
                #pragma unroll
                for (int cc = 0; cc < 4; ++cc) {
                    const int c  = cc * 2 + chalf;
                    const int cz = (c >> 2) & 1;
                    const int cy = (c >> 1) & 1;
                    const int cx = c & 1;
                    const float w = (cz ? f0 : 1.0f - f0) *
                                    (cy ? f1 : 1.0f - f1) *
                                    (cx ? f2 : 1.0f - f2);
                    const int corner = ((i0x + cz) * 4 + (i0y + cy)) * 4 + (i0z + cx);
                    acc[corner * CIN + ch] += w * psi;
                }
            }
        }
        if (lane == 0) den_s[vloc] = (den != 0.0f) ? den : 1.0f;
    }

    __syncthreads();

    // ---- phase 2: C[16 voxels][32 couts] = A[16][1024] x W[1024][32] ----
    // thread (vloc = tid>>4, cp = tid&15) computes couts {2cp, 2cp+1}
    {
        const int vloc = tid >> 4;
        const int cp   = tid & 15;
        const float* A  = A_s + vloc * A_STRIDE;
        const float* Wp = W_s + 2 * cp;

        float c0 = 0.f, c1 = 0.f;
        #pragma unroll 8
        for (int k = 0; k < KDIM; k += 4) {
            const float4 a = *reinterpret_cast<const float4*>(A + k);
            const float2 b0 = *reinterpret_cast<const float2*>(Wp + (k + 0) * COUT);
            const float2 b1 = *reinterpret_cast<const float2*>(Wp + (k + 1) * COUT);
            const float2 b2 = *reinterpret_cast<const float2*>(Wp + (k + 2) * COUT);
            const float2 b3 = *reinterpret_cast<const float2*>(Wp + (k + 3) * COUT);
            c0 = fmaf(a.x, b0.x, c0);  c1 = fmaf(a.x, b0.y, c1);
            c0 = fmaf(a.y, b1.x, c0);  c1 = fmaf(a.y, b1.y, c1);
            c0 = fmaf(a.z, b2.x, c0);  c1 = fmaf(a.z, b2.y, c1);
            c0 = fmaf(a.w, b3.x, c0);  c1 = fmaf(a.w, b3.y, c1);
        }

        const int v = blockIdx.x * VPB + vloc;
        if (v < n_out) {
            const float inv_den = 1.0f / den_s[vloc];
            float y0 = c0 * inv_den + bias[2 * cp + 0];
            float y1 = c1 * inv_den + bias[2 * cp + 1];
            float2 r;
            r.x = fmaxf(y0, 0.0f);
            r.y = fmaxf(y1, 0.0f);
            *reinterpret_cast<float2*>(out + v * COUT + 2 * cp) = r;
        }
    }
}

extern "C" void kernel_launch(void* const* d_in, const int* in_sizes, int n_in,
                              void* d_out, int out_size)
{
    const float* feats        = (const float*)d_in[0];
    const float* inp_points   = (const float*)d_in[1];
    const float* out_points   = (const float*)d_in[2];
    const float* out_extents  = (const float*)d_in[3];
    const float* scale_compat = (const float*)d_in[4];
    const float* nbr_dist     = (const float*)d_in[5];
    const int*   nbr_idx      = (const int*)d_in[6];
    const int*   row_splits   = (const int*)d_in[7];
    const float* Wg           = (const float*)d_in[8];
    const float* bias         = (const float*)d_in[9];
    float*       out          = (float*)d_out;

    const int n_out = in_sizes[7] - 1;

    const size_t smem_bytes = SMEM_FLOATS * sizeof(float);
    cudaFuncSetAttribute(cconv_kernel,
                         cudaFuncAttributeMaxDynamicSharedMemorySize,
                         (int)smem_bytes);

    const int grid = (n_out + VPB - 1) / VPB;
    cconv_kernel<<<grid, THREADS, smem_bytes>>>(
        feats, inp_points, out_points, out_extents, scale_compat,
        nbr_dist, nbr_idx, row_splits, Wg, bias, out, n_out);
}

// round 3
// speedup vs baseline: 1.6467x; 1.6467x over previous
#include <cuda_runtime.h>
#include <math.h>

#define CIN      16
#define COUT     32
#define TAPS     64
#define KDIM     (TAPS * CIN)     // 1024
#define VPB      16               // voxels per block
#define THREADS  256
#define A_STRIDE 1024

// dynamic smem layout:
//  W_s   : KDIM*COUT floats (131072 B), layout [k][cout]
//  A_s   : VPB * A_STRIDE floats (65536 B)
//  den_s : VPB floats
#define SMEM_FLOATS (KDIM * COUT + VPB * A_STRIDE + VPB)

extern __shared__ float smem[];

__global__ void __launch_bounds__(THREADS, 1)
cconv_kernel(const float* __restrict__ feats,
             const float* __restrict__ inp_points,
             const float* __restrict__ out_points,
             const float* __restrict__ out_extents,
             const float* __restrict__ scale_compat,
             const float* __restrict__ nbr_dist,
             const int*   __restrict__ nbr_idx,
             const int*   __restrict__ row_splits,
             const float* __restrict__ Wg,
             const float* __restrict__ bias,
             float*       __restrict__ out,
             int n_out)
{
    float* W_s   = smem;
    float* A_s   = smem + KDIM * COUT;
    float* den_s = A_s + VPB * A_STRIDE;

    const int tid  = threadIdx.x;
    const int warp = tid >> 5;
    const int lane = tid & 31;

    // ---- stage W into shared (coalesced float4; L2-resident after wave 1) ----
    {
        const float4* Wg4 = reinterpret_cast<const float4*>(Wg);
        float4*       Ws4 = reinterpret_cast<float4*>(W_s);
        #pragma unroll 8
        for (int i = 0; i < (KDIM * COUT / 4) / THREADS; ++i)
            Ws4[tid + i * THREADS] = Wg4[tid + i * THREADS];
    }

    // ---- phase 1: per-warp voxel scatter, lane-parallel edge geometry ----
    const int ch    = lane & 15;   // channel 0..15
    const int chalf = lane >> 4;   // corner-half 0/1

    for (int vi = 0; vi < 2; ++vi) {
        const int vloc = warp * 2 + vi;
        const int v    = blockIdx.x * VPB + vloc;
        float* acc = A_s + vloc * A_STRIDE;

        // zero acc row
        float4* acc4 = reinterpret_cast<float4*>(acc);
        #pragma unroll
        for (int i = 0; i < (KDIM / 4) / 32; ++i)
            acc4[lane + i * 32] = make_float4(0.f, 0.f, 0.f, 0.f);

        float den_acc = 0.f;
        if (v < n_out) {
            const int e0  = row_splits[v];
            const int cnt = row_splits[v + 1] - e0;
            const float ox = out_points[v * 3 + 0];
            const float oy = out_points[v * 3 + 1];
            const float oz = out_points[v * 3 + 2];
            const float inv_r = 2.0f / out_extents[v];

            for (int base = 0; base < cnt; base += 16) {
                const int m = min(16, cnt - base);

                // -- per-lane edge geometry (lanes 0..m-1, fully parallel) --
                float imp_l = 0.f, f0_l = 0.f, f1_l = 0.f, f2_l = 0.f;
                int   nb_l  = 0,   cb_l = 0;
                if (lane < m) {
                    const int e = e0 + base + lane;
                    const float sc = scale_compat[e];
                    const float d  = nbr_dist[e];
                    float omr = 1.0f - d;
                    float w6  = omr * omr * omr;
                    w6 = fminf(fmaxf(w6, 0.0f), 1.0f);
                    imp_l = sc * w6;

                    nb_l = nbr_idx[e];
                    const float rx = (inp_points[nb_l * 3 + 0] - ox) * inv_r;
                    const float ry = (inp_points[nb_l * 3 + 1] - oy) * inv_r;
                    const float rz = (inp_points[nb_l * 3 + 2] - oz) * inv_r;

                    const float l2   = sqrtf(rx * rx + ry * ry + rz * rz);
                    const float linf = fmaxf(fabsf(rx), fmaxf(fabsf(ry), fabsf(rz)));
                    const float s    = (linf > 0.0f) ? (l2 / fmaxf(linf, 1e-12f)) : 0.0f;

                    const float q0 = fminf(fmaxf(rx * s, -1.0f), 1.0f);
                    const float q1 = fminf(fmaxf(ry * s, -1.0f), 1.0f);
                    const float q2 = fminf(fmaxf(rz * s, -1.0f), 1.0f);

                    const float t0 = (q0 + 1.0f) * 1.5f;
                    const float t1 = (q1 + 1.0f) * 1.5f;
                    const float t2 = (q2 + 1.0f) * 1.5f;

                    const float fl0 = fminf(fmaxf(floorf(t0), 0.0f), 2.0f);
                    const float fl1 = fminf(fmaxf(floorf(t1), 0.0f), 2.0f);
                    const float fl2 = fminf(fmaxf(floorf(t2), 0.0f), 2.0f);
                    f0_l = t0 - fl0;
                    f1_l = t1 - fl1;
                    f2_l = t2 - fl2;
                    cb_l = (((int)fl0) * 4 + (int)fl1) * 4 + (int)fl2;
                }
                den_acc += imp_l;

                // -- prefetch feats for all edges in chunk (high MLP) --
                float fv[16];
                #pragma unroll
                for (int e = 0; e < 16; ++e) {
                    const int nb = __shfl_sync(0xffffffffu, nb_l, e);
                    if (e < m) fv[e] = feats[nb * CIN + ch];
                }

                // -- scatter: broadcast per-edge scalars, RMW into acc --
                #pragma unroll
                for (int e = 0; e < 16; ++e) {
                    if (e >= m) break;
                    const float imp = __shfl_sync(0xffffffffu, imp_l, e);
                    const float f0  = __shfl_sync(0xffffffffu, f0_l, e);
                    const float f1  = __shfl_sync(0xffffffffu, f1_l, e);
                    const float f2  = __shfl_sync(0xffffffffu, f2_l, e);
                    const int   cb  = __shfl_sync(0xffffffffu, cb_l, e);
                    const float psi = imp * fv[e];
                    const float g0 = 1.0f - f0, g1 = 1.0f - f1, g2 = 1.0f - f2;

                    #pragma unroll
                    for (int cc = 0; cc < 4; ++cc) {
                        const int c  = cc * 2 + chalf;
                        const int cz = (c >> 2) & 1;
                        const int cy = (c >> 1) & 1;
                        const int cx = c & 1;
                        const float w = (cz ? f0 : g0) * (cy ? f1 : g1) * (cx ? f2 : g2);
                        const int corner = cb + cz * 16 + cy * 4 + cx;
                        acc[corner * CIN + ch] += w * psi;
                    }
                }
            }
        }

        // warp-reduce den (lanes >= m contributed 0)
        #pragma unroll
        for (int off = 16; off > 0; off >>= 1)
            den_acc += __shfl_xor_sync(0xffffffffu, den_acc, off);
        if (lane == 0) den_s[vloc] = (den_acc != 0.0f) ? den_acc : 1.0f;
    }

    __syncthreads();

    // ---- phase 2: warp = 2 voxels, lane = cout ----
    {
        const int v0loc = warp * 2;
        const int v1loc = warp * 2 + 1;
        const float* A0 = A_s + v0loc * A_STRIDE;
        const float* A1 = A_s + v1loc * A_STRIDE;

        float c0 = 0.f, c1 = 0.f;
        #pragma unroll 8
        for (int k = 0; k < KDIM; k += 4) {
            const float4 a0 = *reinterpret_cast<const float4*>(A0 + k);
            const float4 a1 = *reinterpret_cast<const float4*>(A1 + k);
            const float w0 = W_s[(k + 0) * COUT + lane];
            const float w1 = W_s[(k + 1) * COUT + lane];
            const float w2 = W_s[(k + 2) * COUT + lane];
            const float w3 = W_s[(k + 3) * COUT + lane];
            c0 = fmaf(a0.x, w0, c0);  c1 = fmaf(a1.x, w0, c1);
            c0 = fmaf(a0.y, w1, c0);  c1 = fmaf(a1.y, w1, c1);
            c0 = fmaf(a0.z, w2, c0);  c1 = fmaf(a1.z, w2, c1);
            c0 = fmaf(a0.w, w3, c0);  c1 = fmaf(a1.w, w3, c1);
        }

        const float b = bias[lane];
        const int v0 = blockIdx.x * VPB + v0loc;
        const int v1 = blockIdx.x * VPB + v1loc;
        if (v0 < n_out) {
            const float y = c0 / den_s[v0loc] + b;
            out[v0 * COUT + lane] = fmaxf(y, 0.0f);
        }
        if (v1 < n_out) {
            const float y = c1 / den_s[v1loc] + b;
            out[v1 * COUT + lane] = fmaxf(y, 0.0f);
        }
    }
}

extern "C" void kernel_launch(void* const* d_in, const int* in_sizes, int n_in,
                              void* d_out, int out_size)
{
    const float* feats        = (const float*)d_in[0];
    const float* inp_points   = (const float*)d_in[1];
    const float* out_points   = (const float*)d_in[2];
    const float* out_extents  = (const float*)d_in[3];
    const float* scale_compat = (const float*)d_in[4];
    const float* nbr_dist     = (const float*)d_in[5];
    const int*   nbr_idx      = (const int*)d_in[6];
    const int*   row_splits   = (const int*)d_in[7];
    const float* Wg           = (const float*)d_in[8];
    const float* bias         = (const float*)d_in[9];
    float*       out          = (float*)d_out;

    const int n_out = in_sizes[7] - 1;

    const size_t smem_bytes = SMEM_FLOATS * sizeof(float);
    cudaFuncSetAttribute(cconv_kernel,
                         cudaFuncAttributeMaxDynamicSharedMemorySize,
                         (int)smem_bytes);

    const int grid = (n_out + VPB - 1) / VPB;
    cconv_kernel<<<grid, THREADS, smem_bytes>>>(
        feats, inp_points, out_points, out_extents, scale_compat,
        nbr_dist, nbr_idx, row_splits, Wg, bias, out, n_out);
}

// round 4
// speedup vs baseline: 2.2331x; 1.3561x over previous
#include <cuda_runtime.h>
#include <math.h>

#define CIN      16
#define COUT     32
#define TAPS     64
#define KDIM     (TAPS * CIN)     // 1024
#define VPB      16               // voxels per block
#define THREADS  256
#define A_STRIDE 1028             // 1024 + 4 pad (banks spread for vq-strided loads)

// dynamic smem layout:
//  W_s   : KDIM*COUT floats (131072 B), layout [k][cout]
//  A_s   : VPB * A_STRIDE floats (65792 B)
//  P_s   : 8 * VPB * COUT floats (16384 B)  -- per-warp GEMM partials
//  den_s : VPB floats
#define SMEM_FLOATS (KDIM * COUT + VPB * A_STRIDE + 8 * VPB * COUT + VPB)

extern __shared__ float smem[];

__global__ void __launch_bounds__(THREADS, 1)
cconv_kernel(const float* __restrict__ feats,
             const float* __restrict__ inp_points,
             const float* __restrict__ out_points,
             const float* __restrict__ out_extents,
             const float* __restrict__ scale_compat,
             const float* __restrict__ nbr_dist,
             const int*   __restrict__ nbr_idx,
             const int*   __restrict__ row_splits,
             const float* __restrict__ Wg,
             const float* __restrict__ bias,
             float*       __restrict__ out,
             int n_out)
{
    float* W_s   = smem;
    float* A_s   = smem + KDIM * COUT;
    float* P_s   = A_s + VPB * A_STRIDE;
    float* den_s = P_s + 8 * VPB * COUT;

    const int tid  = threadIdx.x;
    const int warp = tid >> 5;
    const int lane = tid & 31;

    // ---- stage W into shared (coalesced float4) ----
    {
        const float4* Wg4 = reinterpret_cast<const float4*>(Wg);
        float4*       Ws4 = reinterpret_cast<float4*>(W_s);
        #pragma unroll 8
        for (int i = 0; i < (KDIM * COUT / 4) / THREADS; ++i)
            Ws4[tid + i * THREADS] = Wg4[tid + i * THREADS];
    }

    // ---- phase 1: per-warp voxel scatter, lane-parallel edge geometry ----
    const int ch    = lane & 15;   // channel 0..15
    const int chalf = lane >> 4;   // corner-half 0/1

    for (int vi = 0; vi < 2; ++vi) {
        const int vloc = warp * 2 + vi;
        const int v    = blockIdx.x * VPB + vloc;
        float* acc = A_s + vloc * A_STRIDE;

        // zero acc row (first 1024 floats; pad never read)
        float4* acc4 = reinterpret_cast<float4*>(acc);
        #pragma unroll
        for (int i = 0; i < (KDIM / 4) / 32; ++i)
            acc4[lane + i * 32] = make_float4(0.f, 0.f, 0.f, 0.f);

        float den_acc = 0.f;
        if (v < n_out) {
            const int e0  = row_splits[v];
            const int cnt = row_splits[v + 1] - e0;
            const float ox = out_points[v * 3 + 0];
            const float oy = out_points[v * 3 + 1];
            const float oz = out_points[v * 3 + 2];
            const float inv_r = 2.0f / out_extents[v];

            for (int base = 0; base < cnt; base += 16) {
                const int m = min(16, cnt - base);

                // -- per-lane edge geometry (lanes 0..m-1, fully parallel) --
                float imp_l = 0.f, f0_l = 0.f, f1_l = 0.f, f2_l = 0.f;
                int   nb_l  = 0,   cb_l = 0;
                if (lane < m) {
                    const int e = e0 + base + lane;
                    const float sc = scale_compat[e];
                    const float d  = nbr_dist[e];
                    float omr = 1.0f - d;
                    float w6  = omr * omr * omr;
                    w6 = fminf(fmaxf(w6, 0.0f), 1.0f);
                    imp_l = sc * w6;

                    nb_l = nbr_idx[e];
                    const float rx = (inp_points[nb_l * 3 + 0] - ox) * inv_r;
                    const float ry = (inp_points[nb_l * 3 + 1] - oy) * inv_r;
                    const float rz = (inp_points[nb_l * 3 + 2] - oz) * inv_r;

                    const float l2   = sqrtf(rx * rx + ry * ry + rz * rz);
                    const float linf = fmaxf(fabsf(rx), fmaxf(fabsf(ry), fabsf(rz)));
                    const float s    = (linf > 0.0f) ? (l2 / fmaxf(linf, 1e-12f)) : 0.0f;

                    const float q0 = fminf(fmaxf(rx * s, -1.0f), 1.0f);
                    const float q1 = fminf(fmaxf(ry * s, -1.0f), 1.0f);
                    const float q2 = fminf(fmaxf(rz * s, -1.0f), 1.0f);

                    const float t0 = (q0 + 1.0f) * 1.5f;
                    const float t1 = (q1 + 1.0f) * 1.5f;
                    const float t2 = (q2 + 1.0f) * 1.5f;

                    const float fl0 = fminf(fmaxf(floorf(t0), 0.0f), 2.0f);
                    const float fl1 = fminf(fmaxf(floorf(t1), 0.0f), 2.0f);
                    const float fl2 = fminf(fmaxf(floorf(t2), 0.0f), 2.0f);
                    f0_l = t0 - fl0;
                    f1_l = t1 - fl1;
                    f2_l = t2 - fl2;
                    cb_l = (((int)fl0) * 4 + (int)fl1) * 4 + (int)fl2;
                }
                den_acc += imp_l;

                // -- prefetch feats for all edges in chunk (high MLP) --
                float fv[16];
                #pragma unroll
                for (int e = 0; e < 16; ++e) {
                    const int nb = __shfl_sync(0xffffffffu, nb_l, e);
                    if (e < m) fv[e] = feats[nb * CIN + ch];
                }

                // -- scatter: broadcast per-edge scalars, RMW into acc --
                #pragma unroll
                for (int e = 0; e < 16; ++e) {
                    if (e >= m) break;
                    const float imp = __shfl_sync(0xffffffffu, imp_l, e);
                    const float f0  = __shfl_sync(0xffffffffu, f0_l, e);
                    const float f1  = __shfl_sync(0xffffffffu, f1_l, e);
                    const float f2  = __shfl_sync(0xffffffffu, f2_l, e);
                    const int   cb  = __shfl_sync(0xffffffffu, cb_l, e);
                    const float psi = imp * fv[e];
                    const float g0 = 1.0f - f0, g1 = 1.0f - f1, g2 = 1.0f - f2;

                    #pragma unroll
                    for (int cc = 0; cc < 4; ++cc) {
                        const int c  = cc * 2 + chalf;
                        const int cz = (c >> 2) & 1;
                        const int cy = (c >> 1) & 1;
                        const int cx = c & 1;
                        const float w = (cz ? f0 : g0) * (cy ? f1 : g1) * (cx ? f2 : g2);
                        const int corner = cb + cz * 16 + cy * 4 + cx;
                        acc[corner * CIN + ch] += w * psi;
                    }
                }
            }
        }

        #pragma unroll
        for (int off = 16; off > 0; off >>= 1)
            den_acc += __shfl_xor_sync(0xffffffffu, den_acc, off);
        if (lane == 0) den_s[vloc] = (den_acc != 0.0f) ? den_acc : 1.0f;
    }

    __syncthreads();

    // ---- phase 2: k-split GEMM. warp w owns k in [w*128, w*128+128).
    //      lane = vq (0..3) + 8*cq (0..7); lane tile: voxels {vq,vq+4,vq+8,vq+12},
    //      couts {4cq..4cq+3}. Double-buffered fragments. ----
    {
        const int kbase = warp * 128;
        const int vq    = lane & 3;
        const int cq    = lane >> 2;

        float acc[4][4];
        #pragma unroll
        for (int i = 0; i < 4; ++i)
            #pragma unroll
            for (int j = 0; j < 4; ++j) acc[i][j] = 0.f;

        float4 af[2][4], wf[2][4];

        // prologue: load chunk 0
        #pragma unroll
        for (int i = 0; i < 4; ++i)
            af[0][i] = *reinterpret_cast<const float4*>(A_s + (vq + 4 * i) * A_STRIDE + kbase);
        #pragma unroll
        for (int j = 0; j < 4; ++j)
            wf[0][j] = *reinterpret_cast<const float4*>(W_s + (kbase + j) * COUT + cq * 4);

        #pragma unroll 2
        for (int kc = 0; kc < 32; ++kc) {
            const int cur = kc & 1;
            const int nxt = cur ^ 1;
            if (kc < 31) {
                const int k = kbase + (kc + 1) * 4;
                #pragma unroll
                for (int i = 0; i < 4; ++i)
                    af[nxt][i] = *reinterpret_cast<const float4*>(A_s + (vq + 4 * i) * A_STRIDE + k);
                #pragma unroll
                for (int j = 0; j < 4; ++j)
                    wf[nxt][j] = *reinterpret_cast<const float4*>(W_s + (k + j) * COUT + cq * 4);
            }
            #pragma unroll
            for (int i = 0; i < 4; ++i) {
                const float4 a = af[cur][i];
                acc[i][0] = fmaf(a.x, wf[cur][0].x, acc[i][0]);
                acc[i][1] = fmaf(a.x, wf[cur][0].y, acc[i][1]);
                acc[i][2] = fmaf(a.x, wf[cur][0].z, acc[i][2]);
                acc[i][3] = fmaf(a.x, wf[cur][0].w, acc[i][3]);
                acc[i][0] = fmaf(a.y, wf[cur][1].x, acc[i][0]);
                acc[i][1] = fmaf(a.y, wf[cur][1].y, acc[i][1]);
                acc[i][2] = fmaf(a.y, wf[cur][1].z, acc[i][2]);
                acc[i][3] = fmaf(a.y, wf[cur][1].w, acc[i][3]);
                acc[i][0] = fmaf(a.z, wf[cur][2].x, acc[i][0]);
                acc[i][1] = fmaf(a.z, wf[cur][2].y, acc[i][1]);
                acc[i][2] = fmaf(a.z, wf[cur][2].z, acc[i][2]);
                acc[i][3] = fmaf(a.z, wf[cur][2].w, acc[i][3]);
                acc[i][0] = fmaf(a.w, wf[cur][3].x, acc[i][0]);
                acc[i][1] = fmaf(a.w, wf[cur][3].y, acc[i][1]);
                acc[i][2] = fmaf(a.w, wf[cur][3].z, acc[i][2]);
                acc[i][3] = fmaf(a.w, wf[cur][3].w, acc[i][3]);
            }
        }

        // store per-warp partials: P_s[warp][v][c]
        #pragma unroll
        for (int i = 0; i < 4; ++i) {
            const int v = vq + 4 * i;
            *reinterpret_cast<float4*>(P_s + (warp * VPB + v) * COUT + cq * 4) =
                make_float4(acc[i][0], acc[i][1], acc[i][2], acc[i][3]);
        }
    }

    __syncthreads();

    // ---- reduce 8 partials, normalize, bias, relu, store ----
    {
        const int v  = tid >> 4;          // 0..15
        const int c0 = (tid & 15) * 2;    // cout pair
        float s0 = 0.f, s1 = 0.f;
        #pragma unroll
        for (int w = 0; w < 8; ++w) {
            const float2 p = *reinterpret_cast<const float2*>(P_s + (w * VPB + v) * COUT + c0);
            s0 += p.x;
            s1 += p.y;
        }
        const int vg = blockIdx.x * VPB + v;
        if (vg < n_out) {
            const float inv_den = 1.0f / den_s[v];
            float y0 = s0 * inv_den + bias[c0 + 0];
            float y1 = s1 * inv_den + bias[c0 + 1];
            float2 r;
            r.x = fmaxf(y0, 0.0f);
            r.y = fmaxf(y1, 0.0f);
            *reinterpret_cast<float2*>(out + vg * COUT + c0) = r;
        }
    }
}

extern "C" void kernel_launch(void* const* d_in, const int* in_sizes, int n_in,
                              void* d_out, int out_size)
{
    const float* feats        = (const float*)d_in[0];
    const float* inp_points   = (const float*)d_in[1];
    const float* out_points   = (const float*)d_in[2];
    const float* out_extents  = (const float*)d_in[3];
    const float* scale_compat = (const float*)d_in[4];
    const float* nbr_dist     = (const float*)d_in[5];
    const int*   nbr_idx      = (const int*)d_in[6];
    const int*   row_splits   = (const int*)d_in[7];
    const float* Wg           = (const float*)d_in[8];
    const float* bias         = (const float*)d_in[9];
    float*       out          = (float*)d_out;

    const int n_out = in_sizes[7] - 1;

    const size_t smem_bytes = SMEM_FLOATS * sizeof(float);
    cudaFuncSetAttribute(cconv_kernel,
                         cudaFuncAttributeMaxDynamicSharedMemorySize,
                         (int)smem_bytes);

    const int grid = (n_out + VPB - 1) / VPB;
    cconv_kernel<<<grid, THREADS, smem_bytes>>>(
        feats, inp_points, out_points, out_extents, scale_compat,
        nbr_dist, nbr_idx, row_splits, Wg, bias, out, n_out);
}

// round 5
// speedup vs baseline: 3.3017x; 1.4785x over previous
#include <cuda_runtime.h>
#include <math.h>

#define CIN      16
#define COUT     32
#define TAPS     64
#define KDIM     (TAPS * CIN)     // 1024
#define VPB      16               // voxels per block
#define THREADS  256
#define A_STRIDE 1028             // 1024 + 4 pad (bank-spread for vq-strided loads)

// dynamic smem layout (no W in smem anymore):
//  A_s   : VPB * A_STRIDE floats (65792 B)
//  P_s   : 8 * VPB * COUT floats (16384 B)  -- per-warp GEMM partials
//  den_s : VPB floats
#define SMEM_FLOATS (VPB * A_STRIDE + 8 * VPB * COUT + VPB)

extern __shared__ float smem[];

__global__ void __launch_bounds__(THREADS, 2)
cconv_kernel(const float* __restrict__ feats,
             const float* __restrict__ inp_points,
             const float* __restrict__ out_points,
             const float* __restrict__ out_extents,
             const float* __restrict__ scale_compat,
             const float* __restrict__ nbr_dist,
             const int*   __restrict__ nbr_idx,
             const int*   __restrict__ row_splits,
             const float* __restrict__ Wg,
             const float* __restrict__ bias,
             float*       __restrict__ out,
             int n_out)
{
    float* A_s   = smem;
    float* P_s   = A_s + VPB * A_STRIDE;
    float* den_s = P_s + 8 * VPB * COUT;

    const int tid  = threadIdx.x;
    const int warp = tid >> 5;
    const int lane = tid & 31;

    // ---- phase 1: per-warp voxel scatter, lane-parallel edge geometry ----
    const int ch    = lane & 15;   // channel 0..15
    const int chalf = lane >> 4;   // corner-half 0/1

    for (int vi = 0; vi < 2; ++vi) {
        const int vloc = warp * 2 + vi;
        const int v    = blockIdx.x * VPB + vloc;
        float* acc = A_s + vloc * A_STRIDE;

        // zero acc row (first 1024 floats; pad never read)
        float4* acc4 = reinterpret_cast<float4*>(acc);
        #pragma unroll
        for (int i = 0; i < (KDIM / 4) / 32; ++i)
            acc4[lane + i * 32] = make_float4(0.f, 0.f, 0.f, 0.f);

        float den_acc = 0.f;
        if (v < n_out) {
            const int e0  = row_splits[v];
            const int cnt = row_splits[v + 1] - e0;
            const float ox = out_points[v * 3 + 0];
            const float oy = out_points[v * 3 + 1];
            const float oz = out_points[v * 3 + 2];
            const float inv_r = 2.0f / out_extents[v];

            for (int base = 0; base < cnt; base += 16) {
                const int m = min(16, cnt - base);

                // -- per-lane edge geometry (lanes 0..m-1, fully parallel) --
                float imp_l = 0.f, f0_l = 0.f, f1_l = 0.f, f2_l = 0.f;
                int   nb_l  = 0,   cb_l = 0;
                if (lane < m) {
                    const int e = e0 + base + lane;
                    const float sc = scale_compat[e];
                    const float d  = nbr_dist[e];
                    float omr = 1.0f - d;
                    float w6  = omr * omr * omr;
                    w6 = fminf(fmaxf(w6, 0.0f), 1.0f);
                    imp_l = sc * w6;

                    nb_l = nbr_idx[e];
                    const float rx = (inp_points[nb_l * 3 + 0] - ox) * inv_r;
                    const float ry = (inp_points[nb_l * 3 + 1] - oy) * inv_r;
                    const float rz = (inp_points[nb_l * 3 + 2] - oz) * inv_r;

                    const float l2   = sqrtf(rx * rx + ry * ry + rz * rz);
                    const float linf = fmaxf(fabsf(rx), fmaxf(fabsf(ry), fabsf(rz)));
                    const float s    = (linf > 0.0f) ? (l2 / fmaxf(linf, 1e-12f)) : 0.0f;

                    const float q0 = fminf(fmaxf(rx * s, -1.0f), 1.0f);
                    const float q1 = fminf(fmaxf(ry * s, -1.0f), 1.0f);
                    const float q2 = fminf(fmaxf(rz * s, -1.0f), 1.0f);

                    const float t0 = (q0 + 1.0f) * 1.5f;
                    const float t1 = (q1 + 1.0f) * 1.5f;
                    const float t2 = (q2 + 1.0f) * 1.5f;

                    const float fl0 = fminf(fmaxf(floorf(t0), 0.0f), 2.0f);
                    const float fl1 = fminf(fmaxf(floorf(t1), 0.0f), 2.0f);
                    const float fl2 = fminf(fmaxf(floorf(t2), 0.0f), 2.0f);
                    f0_l = t0 - fl0;
                    f1_l = t1 - fl1;
                    f2_l = t2 - fl2;
                    cb_l = (((int)fl0) * 4 + (int)fl1) * 4 + (int)fl2;
                }
                den_acc += imp_l;

                // -- prefetch feats for all edges in chunk (high MLP) --
                float fv[16];
                #pragma unroll
                for (int e = 0; e < 16; ++e) {
                    const int nb = __shfl_sync(0xffffffffu, nb_l, e);
                    if (e < m) fv[e] = feats[nb * CIN + ch];
                }

                // -- scatter: broadcast per-edge scalars, RMW into acc --
                #pragma unroll
                for (int e = 0; e < 16; ++e) {
                    if (e >= m) break;
                    const float imp = __shfl_sync(0xffffffffu, imp_l, e);
                    const float f0  = __shfl_sync(0xffffffffu, f0_l, e);
                    const float f1  = __shfl_sync(0xffffffffu, f1_l, e);
                    const float f2  = __shfl_sync(0xffffffffu, f2_l, e);
                    const int   cb  = __shfl_sync(0xffffffffu, cb_l, e);
                    const float psi = imp * fv[e];
                    const float g0 = 1.0f - f0, g1 = 1.0f - f1, g2 = 1.0f - f2;

                    #pragma unroll
                    for (int cc = 0; cc < 4; ++cc) {
                        const int c  = cc * 2 + chalf;
                        const int cz = (c >> 2) & 1;
                        const int cy = (c >> 1) & 1;
                        const int cx = c & 1;
                        const float w = (cz ? f0 : g0) * (cy ? f1 : g1) * (cx ? f2 : g2);
                        const int corner = cb + cz * 16 + cy * 4 + cx;
                        acc[corner * CIN + ch] += w * psi;
                    }
                }
            }
        }

        #pragma unroll
        for (int off = 16; off > 0; off >>= 1)
            den_acc += __shfl_xor_sync(0xffffffffu, den_acc, off);
        if (lane == 0) den_s[vloc] = (den_acc != 0.0f) ? den_acc : 1.0f;
    }

    __syncthreads();

    // ---- phase 2: k-split GEMM. warp w owns k in [w*128, w*128+128).
    //      lane = vq (0..3) + 8*cq (0..7); lane tile: voxels {vq,vq+4,vq+8,vq+12},
    //      couts {4cq..4cq+3}. A from smem, W streamed via LDG (L1/L2-resident).
    {
        const int kbase = warp * 128;
        const int vq    = lane & 3;
        const int cq    = lane >> 2;
        const float* Wp = Wg + kbase * COUT + cq * 4;

        float acc[4][4];
        #pragma unroll
        for (int i = 0; i < 4; ++i)
            #pragma unroll
            for (int j = 0; j < 4; ++j) acc[i][j] = 0.f;

        float4 af[2][4], wf[2][4];

        // prologue: load chunk 0
        #pragma unroll
        for (int i = 0; i < 4; ++i)
            af[0][i] = *reinterpret_cast<const float4*>(A_s + (vq + 4 * i) * A_STRIDE + kbase);
        #pragma unroll
        for (int j = 0; j < 4; ++j)
            wf[0][j] = *reinterpret_cast<const float4*>(Wp + j * COUT);

        #pragma unroll 2
        for (int kc = 0; kc < 32; ++kc) {
            const int cur = kc & 1;
            const int nxt = cur ^ 1;
            if (kc < 31) {
                const int k = kbase + (kc + 1) * 4;
                #pragma unroll
                for (int i = 0; i < 4; ++i)
                    af[nxt][i] = *reinterpret_cast<const float4*>(A_s + (vq + 4 * i) * A_STRIDE + k);
                #pragma unroll
                for (int j = 0; j < 4; ++j)
                    wf[nxt][j] = *reinterpret_cast<const float4*>(Wp + ((kc + 1) * 4 + j) * COUT);
            }
            #pragma unroll
            for (int i = 0; i < 4; ++i) {
                const float4 a = af[cur][i];
                acc[i][0] = fmaf(a.x, wf[cur][0].x, acc[i][0]);
                acc[i][1] = fmaf(a.x, wf[cur][0].y, acc[i][1]);
                acc[i][2] = fmaf(a.x, wf[cur][0].z, acc[i][2]);
                acc[i][3] = fmaf(a.x, wf[cur][0].w, acc[i][3]);
                acc[i][0] = fmaf(a.y, wf[cur][1].x, acc[i][0]);
                acc[i][1] = fmaf(a.y, wf[cur][1].y, acc[i][1]);
                acc[i][2] = fmaf(a.y, wf[cur][1].z, acc[i][2]);
                acc[i][3] = fmaf(a.y, wf[cur][1].w, acc[i][3]);
                acc[i][0] = fmaf(a.z, wf[cur][2].x, acc[i][0]);
                acc[i][1] = fmaf(a.z, wf[cur][2].y, acc[i][1]);
                acc[i][2] = fmaf(a.z, wf[cur][2].z, acc[i][2]);
                acc[i][3] = fmaf(a.z, wf[cur][2].w, acc[i][3]);
                acc[i][0] = fmaf(a.w, wf[cur][3].x, acc[i][0]);
                acc[i][1] = fmaf(a.w, wf[cur][3].y, acc[i][1]);
                acc[i][2] = fmaf(a.w, wf[cur][3].z, acc[i][2]);
                acc[i][3] = fmaf(a.w, wf[cur][3].w, acc[i][3]);
            }
        }

        // store per-warp partials: P_s[warp][v][c]
        #pragma unroll
        for (int i = 0; i < 4; ++i) {
            const int v = vq + 4 * i;
            *reinterpret_cast<float4*>(P_s + (warp * VPB + v) * COUT + cq * 4) =
                make_float4(acc[i][0], acc[i][1], acc[i][2], acc[i][3]);
        }
    }

    __syncthreads();

    // ---- reduce 8 partials, normalize, bias, relu, store ----
    {
        const int v  = tid >> 4;          // 0..15
        const int c0 = (tid & 15) * 2;    // cout pair
        float s0 = 0.f, s1 = 0.f;
        #pragma unroll
        for (int w = 0; w < 8; ++w) {
            const float2 p = *reinterpret_cast<const float2*>(P_s + (w * VPB + v) * COUT + c0);
            s0 += p.x;
            s1 += p.y;
        }
        const int vg = blockIdx.x * VPB + v;
        if (vg < n_out) {
            const float inv_den = 1.0f / den_s[v];
            float y0 = s0 * inv_den + bias[c0 + 0];
            float y1 = s1 * inv_den + bias[c0 + 1];
            float2 r;
            r.x = fmaxf(y0, 0.0f);
            r.y = fmaxf(y1, 0.0f);
            *reinterpret_cast<float2*>(out + vg * COUT + c0) = r;
        }
    }
}

extern "C" void kernel_launch(void* const* d_in, const int* in_sizes, int n_in,
                              void* d_out, int out_size)
{
    const float* feats        = (const float*)d_in[0];
    const float* inp_points   = (const float*)d_in[1];
    const float* out_points   = (const float*)d_in[2];
    const float* out_extents  = (const float*)d_in[3];
    const float* scale_compat = (const float*)d_in[4];
    const float* nbr_dist     = (const float*)d_in[5];
    const int*   nbr_idx      = (const int*)d_in[6];
    const int*   row_splits   = (const int*)d_in[7];
    const float* Wg           = (const float*)d_in[8];
    const float* bias         = (const float*)d_in[9];
    float*       out          = (float*)d_out;

    const int n_out = in_sizes[7] - 1;

    const size_t smem_bytes = SMEM_FLOATS * sizeof(float);
    cudaFuncSetAttribute(cconv_kernel,
                         cudaFuncAttributeMaxDynamicSharedMemorySize,
                         (int)smem_bytes);

    const int grid = (n_out + VPB - 1) / VPB;
    cconv_kernel<<<grid, THREADS, smem_bytes>>>(
        feats, inp_points, out_points, out_extents, scale_compat,
        nbr_dist, nbr_idx, row_splits, Wg, bias, out, n_out);
}

// round 6
// speedup vs baseline: 3.5801x; 1.0843x over previous
#include <cuda_runtime.h>
#include <math.h>

#define CIN      16
#define COUT     32
#define TAPS     64
#define KDIM     (TAPS * CIN)     // 1024
#define VPB      16               // voxels per block
#define THREADS  256
#define A_STRIDE 1028             // 1024 + 4 pad

// dynamic smem layout:
//  A_s   : VPB * A_STRIDE floats            (65792 B)
//  P_s   : 8 * VPB * COUT floats            (16384 B)
//  St4_s : 8 warps * 32 edges * float4      ( 4096 B)
//  Aux_s : 8 warps * 32 edges * uint        ( 1024 B)
//  den_s : VPB floats                       (   64 B)
#define SMEM_FLOATS (VPB * A_STRIDE + 8 * VPB * COUT + 8 * 32 * 4 + 8 * 32 + VPB)

extern __shared__ float smem[];

__global__ void __launch_bounds__(THREADS, 2)
cconv_kernel(const float* __restrict__ feats,
             const float* __restrict__ inp_points,
             const float* __restrict__ out_points,
             const float* __restrict__ out_extents,
             const float* __restrict__ scale_compat,
             const float* __restrict__ nbr_dist,
             const int*   __restrict__ nbr_idx,
             const int*   __restrict__ row_splits,
             const float* __restrict__ Wg,
             const float* __restrict__ bias,
             float*       __restrict__ out,
             int n_out, int n_edges)
{
    float*  A_s   = smem;
    float*  P_s   = A_s + VPB * A_STRIDE;
    float4* St4_s = reinterpret_cast<float4*>(P_s + 8 * VPB * COUT);
    unsigned int* Aux_s = reinterpret_cast<unsigned int*>(P_s + 8 * VPB * COUT + 8 * 32 * 4);
    float*  den_s = reinterpret_cast<float*>(Aux_s + 8 * 32);

    const int tid  = threadIdx.x;
    const int warp = tid >> 5;
    const int lane = tid & 31;

    float4*       myst  = St4_s + warp * 32;
    unsigned int* myaux = Aux_s + warp * 32;

    // ---- zero both acc rows owned by this warp (2048 floats) ----
    {
        float4* acc4 = reinterpret_cast<float4*>(A_s + (warp * 2) * A_STRIDE);
        // rows are contiguous except 4-float pad; zero 2*A_STRIDE to cover pad safely
        #pragma unroll
        for (int i = 0; i < 16; ++i)
            acc4[lane + i * 32] = make_float4(0.f, 0.f, 0.f, 0.f);
        // remaining 2*A_STRIDE - 2048 = 8 floats
        if (lane < 8) (A_s + (warp * 2) * A_STRIDE)[2048 + lane] = 0.f;
    }

    // ---- phase 1a: geometry for BOTH voxels in parallel (half-warp each) ----
    const int vhalf = lane >> 4;           // 0 = voxel A, 1 = voxel B
    const int le    = lane & 15;           // edge slot within voxel
    const int vloc  = warp * 2 + vhalf;
    const int v     = blockIdx.x * VPB + vloc;

    float imp_l = 0.f, f0_l = 0.f, f1_l = 0.f, f2_l = 0.f;
    unsigned int aux_l = 0;
    {
        int e0 = 0, cnt = 0;
        if (v < n_out) {
            e0  = row_splits[v];
            cnt = row_splits[v + 1] - e0;
        }
        const bool act = (le < cnt);
        if (v < n_out) {
            const float ox = out_points[v * 3 + 0];
            const float oy = out_points[v * 3 + 1];
            const float oz = out_points[v * 3 + 2];
            const float inv_r = 2.0f / out_extents[v];

            int e = e0 + le;
            if (e >= n_edges) e = n_edges - 1;

            const float sc = scale_compat[e];
            const float d  = nbr_dist[e];
            float omr = 1.0f - d;
            float w6  = omr * omr * omr;
            w6 = fminf(fmaxf(w6, 0.0f), 1.0f);

            const int nb = nbr_idx[e];
            const float rx = (inp_points[nb * 3 + 0] - ox) * inv_r;
            const float ry = (inp_points[nb * 3 + 1] - oy) * inv_r;
            const float rz = (inp_points[nb * 3 + 2] - oz) * inv_r;

            const float l2   = sqrtf(rx * rx + ry * ry + rz * rz);
            const float linf = fmaxf(fabsf(rx), fmaxf(fabsf(ry), fabsf(rz)));
            const float s    = (linf > 0.0f) ? (l2 / fmaxf(linf, 1e-12f)) : 0.0f;

            const float q0 = fminf(fmaxf(rx * s, -1.0f), 1.0f);
            const float q1 = fminf(fmaxf(ry * s, -1.0f), 1.0f);
            const float q2 = fminf(fmaxf(rz * s, -1.0f), 1.0f);

            const float t0 = (q0 + 1.0f) * 1.5f;
            const float t1 = (q1 + 1.0f) * 1.5f;
            const float t2 = (q2 + 1.0f) * 1.5f;

            const float fl0 = fminf(fmaxf(floorf(t0), 0.0f), 2.0f);
            const float fl1 = fminf(fmaxf(floorf(t1), 0.0f), 2.0f);
            const float fl2 = fminf(fmaxf(floorf(t2), 0.0f), 2.0f);
            f0_l = t0 - fl0;
            f1_l = t1 - fl1;
            f2_l = t2 - fl2;
            const int cb = (((int)fl0) * 4 + (int)fl1) * 4 + (int)fl2;

            imp_l = act ? (sc * w6) : 0.f;
            aux_l = ((unsigned int)cb << 18) | (unsigned int)nb;
        }
    }
    // stage
    myst[lane]  = make_float4(imp_l, f0_l, f1_l, f2_l);
    myaux[lane] = aux_l;

    // den: reduce imp within each half-warp
    {
        float den = imp_l;
        #pragma unroll
        for (int off = 8; off > 0; off >>= 1)
            den += __shfl_xor_sync(0xffffffffu, den, off);
        if (le == 0) den_s[vloc] = (den != 0.0f) ? den : 1.0f;
    }
    __syncwarp();

    // ---- phase 1b: scatter, one voxel at a time, full warp ----
    const int ch    = lane & 15;   // channel
    const int chalf = lane >> 4;   // corner-half

    #pragma unroll
    for (int vi = 0; vi < 2; ++vi) {
        float* acc = A_s + (warp * 2 + vi) * A_STRIDE;
        const int ebase = vi * 16;

        // prefetch feats for all 16 edge slots (high MLP)
        unsigned int auxr[16];
        float fv[16];
        #pragma unroll
        for (int e = 0; e < 16; ++e) {
            auxr[e] = myaux[ebase + e];
            fv[e] = feats[(auxr[e] & 0x3FFFFu) * CIN + ch];
        }

        #pragma unroll
        for (int e = 0; e < 16; ++e) {
            const float4 g = myst[ebase + e];
            const float psi = g.x * fv[e];           // imp * feat (0 if inactive)
            const int   cb  = (int)(auxr[e] >> 18);
            const float g0 = 1.0f - g.y, g1 = 1.0f - g.z, g2 = 1.0f - g.w;

            #pragma unroll
            for (int cc = 0; cc < 4; ++cc) {
                const int c  = cc * 2 + chalf;
                const int cz = (c >> 2) & 1;
                const int cy = (c >> 1) & 1;
                const int cx = c & 1;
                const float w = (cz ? g.y : g0) * (cy ? g.z : g1) * (cx ? g.w : g2);
                const int corner = cb + cz * 16 + cy * 4 + cx;
                acc[corner * CIN + ch] += w * psi;
            }
        }
    }

    __syncthreads();

    // ---- phase 2: k-split GEMM. warp w owns k in [w*128, (w+1)*128).
    //      lane = vq(0..3) + 4*cq(0..7); tile: voxels {vq,vq+4,vq+8,vq+12},
    //      couts {4cq..4cq+3}. A from smem, W via LDG (dedup'd, L2-resident).
    {
        const int kbase = warp * 128;
        const int vq    = lane & 3;
        const int cq    = lane >> 2;
        const float* Wp = Wg + kbase * COUT + cq * 4;

        float acc[4][4];
        #pragma unroll
        for (int i = 0; i < 4; ++i)
            #pragma unroll
            for (int j = 0; j < 4; ++j) acc[i][j] = 0.f;

        float4 af[2][4], wf[2][4];

        #pragma unroll
        for (int i = 0; i < 4; ++i)
            af[0][i] = *reinterpret_cast<const float4*>(A_s + (vq + 4 * i) * A_STRIDE + kbase);
        #pragma unroll
        for (int j = 0; j < 4; ++j)
            wf[0][j] = *reinterpret_cast<const float4*>(Wp + j * COUT);

        #pragma unroll 2
        for (int kc = 0; kc < 32; ++kc) {
            const int cur = kc & 1;
            const int nxt = cur ^ 1;
            if (kc < 31) {
                const int k = kbase + (kc + 1) * 4;
                #pragma unroll
                for (int i = 0; i < 4; ++i)
                    af[nxt][i] = *reinterpret_cast<const float4*>(A_s + (vq + 4 * i) * A_STRIDE + k);
                #pragma unroll
                for (int j = 0; j < 4; ++j)
                    wf[nxt][j] = *reinterpret_cast<const float4*>(Wp + ((kc + 1) * 4 + j) * COUT);
            }
            #pragma unroll
            for (int i = 0; i < 4; ++i) {
                const float4 a = af[cur][i];
                acc[i][0] = fmaf(a.x, wf[cur][0].x, acc[i][0]);
                acc[i][1] = fmaf(a.x, wf[cur][0].y, acc[i][1]);
                acc[i][2] = fmaf(a.x, wf[cur][0].z, acc[i][2]);
                acc[i][3] = fmaf(a.x, wf[cur][0].w, acc[i][3]);
                acc[i][0] = fmaf(a.y, wf[cur][1].x, acc[i][0]);
                acc[i][1] = fmaf(a.y, wf[cur][1].y, acc[i][1]);
                acc[i][2] = fmaf(a.y, wf[cur][1].z, acc[i][2]);
                acc[i][3] = fmaf(a.y, wf[cur][1].w, acc[i][3]);
                acc[i][0] = fmaf(a.z, wf[cur][2].x, acc[i][0]);
                acc[i][1] = fmaf(a.z, wf[cur][2].y, acc[i][1]);
                acc[i][2] = fmaf(a.z, wf[cur][2].z, acc[i][2]);
                acc[i][3] = fmaf(a.z, wf[cur][2].w, acc[i][3]);
                acc[i][0] = fmaf(a.w, wf[cur][3].x, acc[i][0]);
                acc[i][1] = fmaf(a.w, wf[cur][3].y, acc[i][1]);
                acc[i][2] = fmaf(a.w, wf[cur][3].z, acc[i][2]);
                acc[i][3] = fmaf(a.w, wf[cur][3].w, acc[i][3]);
            }
        }

        #pragma unroll
        for (int i = 0; i < 4; ++i) {
            const int vv = vq + 4 * i;
            *reinterpret_cast<float4*>(P_s + (warp * VPB + vv) * COUT + cq * 4) =
                make_float4(acc[i][0], acc[i][1], acc[i][2], acc[i][3]);
        }
    }

    __syncthreads();

    // ---- reduce 8 partials, normalize, bias, relu, store ----
    {
        const int vv = tid >> 4;          // 0..15
        const int c0 = (tid & 15) * 2;    // cout pair
        float s0 = 0.f, s1 = 0.f;
        #pragma unroll
        for (int w = 0; w < 8; ++w) {
            const float2 p = *reinterpret_cast<const float2*>(P_s + (w * VPB + vv) * COUT + c0);
            s0 += p.x;
            s1 += p.y;
        }
        const int vg = blockIdx.x * VPB + vv;
        if (vg < n_out) {
            const float inv_den = 1.0f / den_s[vv];
            float y0 = s0 * inv_den + bias[c0 + 0];
            float y1 = s1 * inv_den + bias[c0 + 1];
            float2 r;
            r.x = fmaxf(y0, 0.0f);
            r.y = fmaxf(y1, 0.0f);
            *reinterpret_cast<float2*>(out + vg * COUT + c0) = r;
        }
    }
}

extern "C" void kernel_launch(void* const* d_in, const int* in_sizes, int n_in,
                              void* d_out, int out_size)
{
    const float* feats        = (const float*)d_in[0];
    const float* inp_points   = (const float*)d_in[1];
    const float* out_points   = (const float*)d_in[2];
    const float* out_extents  = (const float*)d_in[3];
    const float* scale_compat = (const float*)d_in[4];
    const float* nbr_dist     = (const float*)d_in[5];
    const int*   nbr_idx      = (const int*)d_in[6];
    const int*   row_splits   = (const int*)d_in[7];
    const float* Wg           = (const float*)d_in[8];
    const float* bias         = (const float*)d_in[9];
    float*       out          = (float*)d_out;

    const int n_out   = in_sizes[7] - 1;
    const int n_edges = in_sizes[6];

    const size_t smem_bytes = SMEM_FLOATS * sizeof(float);
    cudaFuncSetAttribute(cconv_kernel,
                         cudaFuncAttributeMaxDynamicSharedMemorySize,
                         (int)smem_bytes);

    const int grid = (n_out + VPB - 1) / VPB;
    cconv_kernel<<<grid, THREADS, smem_bytes>>>(
        feats, inp_points, out_points, out_extents, scale_compat,
        nbr_dist, nbr_idx, row_splits, Wg, bias, out, n_out, n_edges);
}